// round 11
// baseline (speedup 1.0000x reference)
#include <cuda_runtime.h>
#include <math.h>
#include <stdint.h>

#define T   2048
#define H   2048
#define E   16
#define IDIM 512
#define IS  2048

// tile geometry: 128(M) x 128(Bcols) x 32(K) per stage, pad rows to 36 words
#define SW        (128 * 36)          // words per tile
#define STAGE_W   (2 * SW)            // A + B
#define NSTAGE    3
#define SMEM_BYTES (NSTAGE * STAGE_W * 4)

// ---------------- scratch (static device memory; no allocation) ----------------
__device__ int   d_cnt[E];
__device__ int   d_list[E][T];
__device__ float d_wt[2 * T];
__device__ float d_sg[T];
__device__ float d_hmid[2 * T * IDIM];   // tf32-bit floats
__device__ float d_contrib[2 * T * H];   // fp32
__device__ float d_hsh[T * IS];          // tf32-bit floats
__device__ float d_shout[T * H];         // fp32

// tf32 pre-converted copies of inputs
__device__ float d_xc[T * H];
__device__ float d_w1c[E * IDIM * H];
__device__ float d_w3c[E * IDIM * H];
__device__ float d_w2c[E * H * IDIM];
__device__ float d_wsgc[IS * H];
__device__ float d_wsuc[IS * H];
__device__ float d_wsdc[H * IS];

// ---------------- helpers ----------------
__device__ __forceinline__ uint32_t f2tf(float f) {
    uint32_t u;
    asm("cvt.rna.tf32.f32 %0, %1;" : "=r"(u) : "f"(f));
    return u;
}
__device__ __forceinline__ void mma8(float c[4], const uint32_t a[4], const uint32_t b[2]) {
    asm volatile(
        "mma.sync.aligned.m16n8k8.row.col.f32.tf32.tf32.f32 "
        "{%0,%1,%2,%3}, {%4,%5,%6,%7}, {%8,%9}, {%0,%1,%2,%3};"
        : "+f"(c[0]), "+f"(c[1]), "+f"(c[2]), "+f"(c[3])
        : "r"(a[0]), "r"(a[1]), "r"(a[2]), "r"(a[3]), "r"(b[0]), "r"(b[1]));
}
__device__ __forceinline__ float silu_f(float x) { return x / (1.f + expf(-x)); }
__device__ __forceinline__ void cpa16(uint32_t dst, const float* src, bool v) {
    int sz = v ? 16 : 0;
    asm volatile("cp.async.cg.shared.global [%0], [%1], 16, %2;\n"
                 :: "r"(dst), "l"(src), "r"(sz));
}
#define CP_COMMIT() asm volatile("cp.async.commit_group;")
#define CP_WAIT1()  asm volatile("cp.async.wait_group 1;")
#define CP_WAIT0()  asm volatile("cp.async.wait_group 0;")

// ---------------- init ----------------
__global__ void init_kernel() {
    if (threadIdx.x < E) d_cnt[threadIdx.x] = 0;
}

// ---------------- tf32 conversion (rna) ----------------
__global__ void convert_kernel(float* __restrict__ dst, const float* __restrict__ src, int n4) {
    int i = blockIdx.x * blockDim.x + threadIdx.x;
    if (i >= n4) return;
    float4 v = ((const float4*)src)[i];
    float4 o;
    o.x = __uint_as_float(f2tf(v.x));
    o.y = __uint_as_float(f2tf(v.y));
    o.z = __uint_as_float(f2tf(v.z));
    o.w = __uint_as_float(f2tf(v.w));
    ((float4*)dst)[i] = o;
}

// ---------------- router: one warp per token (fp32) ----------------
__global__ void router_kernel(const float* __restrict__ x,
                              const float* __restrict__ gw,
                              const float* __restrict__ sgw) {
    int warp = threadIdx.x >> 5, lane = threadIdx.x & 31;
    int t = blockIdx.x * (blockDim.x >> 5) + warp;
    if (t >= T) return;

    float acc[E];
#pragma unroll
    for (int e = 0; e < E; e++) acc[e] = 0.f;
    float g = 0.f;

    const float* xr = x + (size_t)t * H;
    for (int h = lane; h < H; h += 32) {
        float xv = xr[h];
        g = fmaf(xv, sgw[h], g);
#pragma unroll
        for (int e = 0; e < E; e++) acc[e] = fmaf(xv, gw[e * H + h], acc[e]);
    }
#pragma unroll
    for (int e = 0; e < E; e++) {
#pragma unroll
        for (int o = 16; o; o >>= 1) acc[e] += __shfl_xor_sync(0xffffffffu, acc[e], o);
    }
#pragma unroll
    for (int o = 16; o; o >>= 1) g += __shfl_xor_sync(0xffffffffu, g, o);

    if (lane == 0) {
        float m = acc[0];
#pragma unroll
        for (int e = 1; e < E; e++) m = fmaxf(m, acc[e]);
        float p[E];
#pragma unroll
        for (int e = 0; e < E; e++) p[e] = expf(acc[e] - m);
        int i0 = 0; float p0 = p[0];
#pragma unroll
        for (int e = 1; e < E; e++) if (p[e] > p0) { p0 = p[e]; i0 = e; }
        int i1 = -1; float p1 = -1.f;
#pragma unroll
        for (int e = 0; e < E; e++) {
            if (e == i0) continue;
            if (p[e] > p1) { p1 = p[e]; i1 = e; }
        }
        float denom = p0 + p1;
        d_wt[t * 2 + 0] = p0 / denom;
        d_wt[t * 2 + 1] = p1 / denom;
        int q0 = atomicAdd(&d_cnt[i0], 1);
        d_list[i0][q0] = t * 2 + 0;
        int q1 = atomicAdd(&d_cnt[i1], 1);
        d_list[i1][q1] = t * 2 + 1;
        d_sg[t] = g;
    }
}

// =================================================================
// GEMM compute core (shared by all kernels via macro):
// 8 warps (4M x 2N), warp tile 32 x 64, block 128 x 128smemcols x 32K
// =================================================================
#define GEMM_COMPUTE(sA, sB)                                            \
    _Pragma("unroll")                                                   \
    for (int ks = 0; ks < 4; ks++) {                                    \
        int kk = ks * 8 + tig;                                          \
        uint32_t a[2][4];                                               \
        _Pragma("unroll")                                               \
        for (int mi = 0; mi < 2; mi++) {                                \
            int r0 = wm + mi * 16 + gid;                                \
            a[mi][0] = sA[r0 * 36 + kk];                                \
            a[mi][1] = sA[(r0 + 8) * 36 + kk];                          \
            a[mi][2] = sA[r0 * 36 + kk + 4];                            \
            a[mi][3] = sA[(r0 + 8) * 36 + kk + 4];                      \
        }                                                               \
        _Pragma("unroll")                                               \
        for (int ni = 0; ni < 8; ni++) {                                \
            int rb = wn + ni * 8 + gid;                                 \
            uint32_t b[2] = { sB[rb * 36 + kk], sB[rb * 36 + kk + 4] }; \
            mma8(acc[0][ni], a[0], b);                                  \
            mma8(acc[1][ni], a[1], b);                                  \
        }                                                               \
    }

// =================================================================
// expert up/gate: A = gathered d_xc rows, B = interleaved w1c/w3c
// grid (IDIM/64, 16, E), 256 threads
// =================================================================
__global__ __launch_bounds__(256, 2)
void expert_up_mma() {
    extern __shared__ float smh[];
    __shared__ int rows[128];
    int e = blockIdx.z;
    int M = d_cnt[e];
    int m0 = blockIdx.y * 128;
    if (m0 >= M) return;
    int n0 = blockIdx.x * 64;

    int tid = threadIdx.x;
    if (tid < 128) { int m = m0 + tid; rows[tid] = (m < M) ? d_list[e][m] : -1; }
    __syncthreads();

    uint32_t sbase = (uint32_t)__cvta_generic_to_shared(smh);
    int lrow = tid >> 1;
    int koff = (tid & 1) * 16;
    int enc0 = rows[lrow];
    bool aval = enc0 >= 0;
    const float* aptr = d_xc + (aval ? (size_t)(enc0 >> 1) * H : 0) + koff;
    int mat = (lrow >> 3) & 1;
    int colIdx = (lrow >> 4) * 8 + (lrow & 7);
    const float* bptr = (mat ? d_w3c : d_w1c) + ((size_t)e * IDIM + n0 + colIdx) * H + koff;
    uint32_t adst = sbase + (uint32_t)(lrow * 36 + koff) * 4u;
    uint32_t bdst = adst + SW * 4u;

    int warp = tid >> 5, lane = tid & 31;
    int wm = (warp & 3) << 5, wn = (warp >> 2) << 6;
    int gid = lane >> 2, tig = lane & 3;
    float acc[2][8][4] = {};

    auto issue = [&](int s, int kt) {
        uint32_t so = (uint32_t)s * (STAGE_W * 4u);
        const float* ap = aptr + kt * 32;
        const float* bp = bptr + kt * 32;
#pragma unroll
        for (int i = 0; i < 4; i++) cpa16(adst + so + i * 16, ap + i * 4, aval);
#pragma unroll
        for (int i = 0; i < 4; i++) cpa16(bdst + so + i * 16, bp + i * 4, true);
    };

    issue(0, 0); CP_COMMIT();
    issue(1, 1); CP_COMMIT();

    const int KT = H / 32;
    int st = 0;
    for (int k = 0; k < KT; k++) {
        CP_WAIT1();
        __syncthreads();
        const uint32_t* sA = (const uint32_t*)smh + st * STAGE_W;
        const uint32_t* sB = sA + SW;
        GEMM_COMPUTE(sA, sB);
        int nk = k + 2;
        if (nk < KT) { int s2 = st + 2; if (s2 >= 3) s2 -= 3; issue(s2, nk); }
        CP_COMMIT();
        st = (st == 2) ? 0 : st + 1;
    }
    CP_WAIT0();

#pragma unroll
    for (int mi = 0; mi < 2; mi++)
#pragma unroll
        for (int hh = 0; hh < 2; hh++) {
            int r = wm + mi * 16 + gid + 8 * hh;
            int enc = rows[r];
            if (enc < 0) continue;
            float* base = d_hmid + (size_t)enc * IDIM;
#pragma unroll
            for (int nip = 0; nip < 4; nip++) {
                int col = n0 + ((wn >> 4) + nip) * 8 + tig * 2;
                float g0 = acc[mi][2 * nip][2 * hh],     g1 = acc[mi][2 * nip][2 * hh + 1];
                float u0 = acc[mi][2 * nip + 1][2 * hh], u1 = acc[mi][2 * nip + 1][2 * hh + 1];
                float2 v;
                v.x = __uint_as_float(f2tf(silu_f(g0) * u0));
                v.y = __uint_as_float(f2tf(silu_f(g1) * u1));
                *(float2*)(base + col) = v;
            }
        }
}

// =================================================================
// expert down: A = gathered d_hmid rows, B = w2c, weighted epilogue
// grid (H/128, 16, E), 256 threads
// =================================================================
__global__ __launch_bounds__(256, 2)
void expert_down_mma() {
    extern __shared__ float smh[];
    __shared__ int rows[128];
    int e = blockIdx.z;
    int M = d_cnt[e];
    int m0 = blockIdx.y * 128;
    if (m0 >= M) return;
    int n0 = blockIdx.x * 128;

    int tid = threadIdx.x;
    if (tid < 128) { int m = m0 + tid; rows[tid] = (m < M) ? d_list[e][m] : -1; }
    __syncthreads();

    uint32_t sbase = (uint32_t)__cvta_generic_to_shared(smh);
    int lrow = tid >> 1;
    int koff = (tid & 1) * 16;
    int enc0 = rows[lrow];
    bool aval = enc0 >= 0;
    const float* aptr = d_hmid + (aval ? (size_t)enc0 * IDIM : 0) + koff;
    const float* bptr = d_w2c + ((size_t)e * H + n0 + lrow) * IDIM + koff;
    uint32_t adst = sbase + (uint32_t)(lrow * 36 + koff) * 4u;
    uint32_t bdst = adst + SW * 4u;

    int warp = tid >> 5, lane = tid & 31;
    int wm = (warp & 3) << 5, wn = (warp >> 2) << 6;
    int gid = lane >> 2, tig = lane & 3;
    float acc[2][8][4] = {};

    auto issue = [&](int s, int kt) {
        uint32_t so = (uint32_t)s * (STAGE_W * 4u);
        const float* ap = aptr + kt * 32;
        const float* bp = bptr + kt * 32;
#pragma unroll
        for (int i = 0; i < 4; i++) cpa16(adst + so + i * 16, ap + i * 4, aval);
#pragma unroll
        for (int i = 0; i < 4; i++) cpa16(bdst + so + i * 16, bp + i * 4, true);
    };

    issue(0, 0); CP_COMMIT();
    issue(1, 1); CP_COMMIT();

    const int KT = IDIM / 32;
    int st = 0;
    for (int k = 0; k < KT; k++) {
        CP_WAIT1();
        __syncthreads();
        const uint32_t* sA = (const uint32_t*)smh + st * STAGE_W;
        const uint32_t* sB = sA + SW;
        GEMM_COMPUTE(sA, sB);
        int nk = k + 2;
        if (nk < KT) { int s2 = st + 2; if (s2 >= 3) s2 -= 3; issue(s2, nk); }
        CP_COMMIT();
        st = (st == 2) ? 0 : st + 1;
    }
    CP_WAIT0();

#pragma unroll
    for (int mi = 0; mi < 2; mi++)
#pragma unroll
        for (int hh = 0; hh < 2; hh++) {
            int r = wm + mi * 16 + gid + 8 * hh;
            int enc = rows[r];
            if (enc < 0) continue;
            float w = d_wt[enc];
            float* dst = d_contrib + (size_t)enc * H + n0 + wn + tig * 2;
#pragma unroll
            for (int ni = 0; ni < 8; ni++) {
                float2 v = make_float2(w * acc[mi][ni][2 * hh], w * acc[mi][ni][2 * hh + 1]);
                *(float2*)(dst + ni * 8) = v;
            }
        }
}

// =================================================================
// shared up/gate: dense A = d_xc, B = interleaved wsgc/wsuc
// grid (IS/64, 16), 256 threads
// =================================================================
__global__ __launch_bounds__(256, 2)
void shared_up_mma() {
    extern __shared__ float smh[];
    int m0 = blockIdx.y * 128;
    int n0 = blockIdx.x * 64;

    int tid = threadIdx.x;
    uint32_t sbase = (uint32_t)__cvta_generic_to_shared(smh);
    int lrow = tid >> 1;
    int koff = (tid & 1) * 16;
    const float* aptr = d_xc + (size_t)(m0 + lrow) * H + koff;
    int mat = (lrow >> 3) & 1;
    int colIdx = (lrow >> 4) * 8 + (lrow & 7);
    const float* bptr = (mat ? d_wsuc : d_wsgc) + (size_t)(n0 + colIdx) * H + koff;
    uint32_t adst = sbase + (uint32_t)(lrow * 36 + koff) * 4u;
    uint32_t bdst = adst + SW * 4u;

    int warp = tid >> 5, lane = tid & 31;
    int wm = (warp & 3) << 5, wn = (warp >> 2) << 6;
    int gid = lane >> 2, tig = lane & 3;
    float acc[2][8][4] = {};

    auto issue = [&](int s, int kt) {
        uint32_t so = (uint32_t)s * (STAGE_W * 4u);
        const float* ap = aptr + kt * 32;
        const float* bp = bptr + kt * 32;
#pragma unroll
        for (int i = 0; i < 4; i++) cpa16(adst + so + i * 16, ap + i * 4, true);
#pragma unroll
        for (int i = 0; i < 4; i++) cpa16(bdst + so + i * 16, bp + i * 4, true);
    };

    issue(0, 0); CP_COMMIT();
    issue(1, 1); CP_COMMIT();

    const int KT = H / 32;
    int st = 0;
    for (int k = 0; k < KT; k++) {
        CP_WAIT1();
        __syncthreads();
        const uint32_t* sA = (const uint32_t*)smh + st * STAGE_W;
        const uint32_t* sB = sA + SW;
        GEMM_COMPUTE(sA, sB);
        int nk = k + 2;
        if (nk < KT) { int s2 = st + 2; if (s2 >= 3) s2 -= 3; issue(s2, nk); }
        CP_COMMIT();
        st = (st == 2) ? 0 : st + 1;
    }
    CP_WAIT0();

#pragma unroll
    for (int mi = 0; mi < 2; mi++)
#pragma unroll
        for (int hh = 0; hh < 2; hh++) {
            int r = m0 + wm + mi * 16 + gid + 8 * hh;
            float* base = d_hsh + (size_t)r * IS;
#pragma unroll
            for (int nip = 0; nip < 4; nip++) {
                int col = n0 + ((wn >> 4) + nip) * 8 + tig * 2;
                float g0 = acc[mi][2 * nip][2 * hh],     g1 = acc[mi][2 * nip][2 * hh + 1];
                float u0 = acc[mi][2 * nip + 1][2 * hh], u1 = acc[mi][2 * nip + 1][2 * hh + 1];
                float2 v;
                v.x = __uint_as_float(f2tf(silu_f(g0) * u0));
                v.y = __uint_as_float(f2tf(silu_f(g1) * u1));
                *(float2*)(base + col) = v;
            }
        }
}

// =================================================================
// shared down: dense A = d_hsh, B = wsdc
// grid (H/128, 16), 256 threads
// =================================================================
__global__ __launch_bounds__(256, 2)
void shared_down_mma() {
    extern __shared__ float smh[];
    int m0 = blockIdx.y * 128;
    int n0 = blockIdx.x * 128;

    int tid = threadIdx.x;
    uint32_t sbase = (uint32_t)__cvta_generic_to_shared(smh);
    int lrow = tid >> 1;
    int koff = (tid & 1) * 16;
    const float* aptr = d_hsh + (size_t)(m0 + lrow) * IS + koff;
    const float* bptr = d_wsdc + (size_t)(n0 + lrow) * IS + koff;
    uint32_t adst = sbase + (uint32_t)(lrow * 36 + koff) * 4u;
    uint32_t bdst = adst + SW * 4u;

    int warp = tid >> 5, lane = tid & 31;
    int wm = (warp & 3) << 5, wn = (warp >> 2) << 6;
    int gid = lane >> 2, tig = lane & 3;
    float acc[2][8][4] = {};

    auto issue = [&](int s, int kt) {
        uint32_t so = (uint32_t)s * (STAGE_W * 4u);
        const float* ap = aptr + kt * 32;
        const float* bp = bptr + kt * 32;
#pragma unroll
        for (int i = 0; i < 4; i++) cpa16(adst + so + i * 16, ap + i * 4, true);
#pragma unroll
        for (int i = 0; i < 4; i++) cpa16(bdst + so + i * 16, bp + i * 4, true);
    };

    issue(0, 0); CP_COMMIT();
    issue(1, 1); CP_COMMIT();

    const int KT = IS / 32;
    int st = 0;
    for (int k = 0; k < KT; k++) {
        CP_WAIT1();
        __syncthreads();
        const uint32_t* sA = (const uint32_t*)smh + st * STAGE_W;
        const uint32_t* sB = sA + SW;
        GEMM_COMPUTE(sA, sB);
        int nk = k + 2;
        if (nk < KT) { int s2 = st + 2; if (s2 >= 3) s2 -= 3; issue(s2, nk); }
        CP_COMMIT();
        st = (st == 2) ? 0 : st + 1;
    }
    CP_WAIT0();

#pragma unroll
    for (int mi = 0; mi < 2; mi++)
#pragma unroll
        for (int hh = 0; hh < 2; hh++) {
            int r = m0 + wm + mi * 16 + gid + 8 * hh;
            float* dst = d_shout + (size_t)r * H + n0 + wn + tig * 2;
#pragma unroll
            for (int ni = 0; ni < 8; ni++) {
                float2 v = make_float2(acc[mi][ni][2 * hh], acc[mi][ni][2 * hh + 1]);
                *(float2*)(dst + ni * 8) = v;
            }
        }
}

// ---------------- combine ----------------
__global__ void combine_kernel(float* __restrict__ out) {
    int i = blockIdx.x * blockDim.x + threadIdx.x;
    int t = i / (H / 4);
    int c = (i % (H / 4)) * 4;
    float4 a = *(const float4*)(d_contrib + (size_t)(2 * t + 0) * H + c);
    float4 b = *(const float4*)(d_contrib + (size_t)(2 * t + 1) * H + c);
    float4 s = *(const float4*)(d_shout + (size_t)t * H + c);
    float sg = 1.f / (1.f + expf(-d_sg[t]));
    float4 o;
    o.x = a.x + b.x + sg * s.x;
    o.y = a.y + b.y + sg * s.y;
    o.z = a.z + b.z + sg * s.z;
    o.w = a.w + b.w + sg * s.w;
    ((float4*)out)[i] = o;
}

// ---------------- launch ----------------
extern "C" void kernel_launch(void* const* d_in, const int* in_sizes, int n_in,
                              void* d_out, int out_size) {
    (void)in_sizes; (void)n_in; (void)out_size;
    const float* x        = (const float*)d_in[0];
    const float* gate_w   = (const float*)d_in[1];
    const float* w1       = (const float*)d_in[2];
    const float* w2       = (const float*)d_in[3];
    const float* w3       = (const float*)d_in[4];
    const float* ws_gate  = (const float*)d_in[5];
    const float* ws_up    = (const float*)d_in[6];
    const float* ws_down  = (const float*)d_in[7];
    const float* sgw      = (const float*)d_in[8];
    float* out = (float*)d_out;

    cudaFuncSetAttribute(expert_up_mma,   cudaFuncAttributeMaxDynamicSharedMemorySize, SMEM_BYTES);
    cudaFuncSetAttribute(expert_down_mma, cudaFuncAttributeMaxDynamicSharedMemorySize, SMEM_BYTES);
    cudaFuncSetAttribute(shared_up_mma,   cudaFuncAttributeMaxDynamicSharedMemorySize, SMEM_BYTES);
    cudaFuncSetAttribute(shared_down_mma, cudaFuncAttributeMaxDynamicSharedMemorySize, SMEM_BYTES);

    float* xc;   cudaGetSymbolAddress((void**)&xc,   d_xc);
    float* w1c;  cudaGetSymbolAddress((void**)&w1c,  d_w1c);
    float* w3c;  cudaGetSymbolAddress((void**)&w3c,  d_w3c);
    float* w2c;  cudaGetSymbolAddress((void**)&w2c,  d_w2c);
    float* wsgc; cudaGetSymbolAddress((void**)&wsgc, d_wsgc);
    float* wsuc; cudaGetSymbolAddress((void**)&wsuc, d_wsuc);
    float* wsdc; cudaGetSymbolAddress((void**)&wsdc, d_wsdc);

    init_kernel<<<1, 32>>>();
    router_kernel<<<T / 4, 128>>>(x, gate_w, sgw);

    convert_kernel<<<(T * H / 4) / 256, 256>>>(xc, x, T * H / 4);
    convert_kernel<<<(E * IDIM * H / 4) / 256, 256>>>(w1c, w1, E * IDIM * H / 4);
    convert_kernel<<<(E * IDIM * H / 4) / 256, 256>>>(w3c, w3, E * IDIM * H / 4);
    convert_kernel<<<(E * H * IDIM / 4) / 256, 256>>>(w2c, w2, E * H * IDIM / 4);
    convert_kernel<<<(IS * H / 4) / 256, 256>>>(wsgc, ws_gate, IS * H / 4);
    convert_kernel<<<(IS * H / 4) / 256, 256>>>(wsuc, ws_up, IS * H / 4);
    convert_kernel<<<(H * IS / 4) / 256, 256>>>(wsdc, ws_down, H * IS / 4);

    expert_up_mma<<<dim3(IDIM / 64, 16, E), 256, SMEM_BYTES>>>();
    expert_down_mma<<<dim3(H / 128, 16, E), 256, SMEM_BYTES>>>();
    shared_up_mma<<<dim3(IS / 64, 16), 256, SMEM_BYTES>>>();
    shared_down_mma<<<dim3(H / 128, 16), 256, SMEM_BYTES>>>();
    combine_kernel<<<(T * H / 4) / 256, 256>>>(out);
}